// round 14
// baseline (speedup 1.0000x reference)
#include <cuda_runtime.h>
#include <cuda_fp16.h>
#include <cstdint>

// Problem geometry: velocity (B=2, D=128, H=128, W=128, C=3) float32
#define B_  2
#define DIM 128
#define VOX_PER_B (DIM * DIM * DIM)          // 2097152 = 1<<21
#define N_VOX (B_ * VOX_PER_B)               // 4194304
#define ZHALF (64 << 14)

// Ping-pong scratch: 8 B/voxel = (half2(vz,vy), half2(vx,0)) packed in uint2
__device__ uint2 g_bufA[N_VOX];
__device__ uint2 g_bufB[N_VOX];

static __device__ __forceinline__ uint2 pack_v(float vz, float vy, float vx)
{
    __half2 h0 = __floats2half2_rn(vz, vy);
    __half2 h1 = __floats2half2_rn(vx, 0.f);
    uint2 r;
    r.x = *(const unsigned int*)&h0;
    r.y = *(const unsigned int*)&h1;
    return r;
}

// -------- convert: float3 AoS fp32 input -> packed fp16, fused 1/2^STEPS scale --------
__global__ __launch_bounds__(256)
void convert_kernel(const float* __restrict__ in, uint2* __restrict__ out, float s)
{
    int t = blockIdx.x * blockDim.x + threadIdx.x;   // one thread = 4 voxels
    if (t >= N_VOX / 4) return;
    const float4* in4 = (const float4*)in;
    float4 a = in4[t * 3 + 0];
    float4 b = in4[t * 3 + 1];
    float4 c = in4[t * 3 + 2];
    out[t * 4 + 0] = pack_v(a.x * s, a.y * s, a.z * s);
    out[t * 4 + 1] = pack_v(a.w * s, b.x * s, b.y * s);
    out[t * 4 + 2] = pack_v(b.z * s, b.w * s, c.x * s);
    out[t * 4 + 3] = pack_v(c.y * s, c.z * s, c.w * s);
}

// ================= tiled squaring step: 16^3 tile + halo H, smem gathers ============
// Valid when |v| < H for every voxel (guaranteed: |v_k| <= max|input| * 2^k / 256).
template <int H>
__global__ __launch_bounds__(512, 3)
void gridexp_tile(const uint2* __restrict__ src, uint2* __restrict__ dst)
{
    constexpr int EXT = 16 + 2 * H;     // tile+halo extent per dim
    constexpr int YS  = EXT + 1;        // padded y-stride (elements) — bank spread
    constexpr int ZS  = EXT * YS;       // z-stride
    extern __shared__ uint2 sm[];

    const int bx = blockIdx.x, by = blockIdx.y;
    const int bz = blockIdx.z & 7;
    const int b  = blockIdx.z >> 3;
    const int base = b << 21;
    const int gx0 = bx * 16 - H;
    const int gy0 = by * 16 - H;
    const int gz0 = bz * 16 - H;

    // ---- cooperative wrapped halo load (coalesced in x) ----
    constexpr int NELEM = EXT * EXT * EXT;
    for (int i = threadIdx.x; i < NELEM; i += 512) {
        int lz  = i / (EXT * EXT);                 // const divisor -> IMAD.HI
        int rem = i - lz * (EXT * EXT);
        int ly  = rem / EXT;
        int lxx = rem - ly * EXT;
        int gz = (gz0 + lz) & 127;
        int gy = (gy0 + ly) & 127;
        int gx = (gx0 + lxx) & 127;
        sm[lz * ZS + ly * YS + lxx] =
            __ldg(src + (base + (gz << 14) + (gy << 7) + gx));
    }
    __syncthreads();

    const int lx   = threadIdx.x & 15;
    const int ly   = (threadIdx.x >> 4) & 15;
    const int zpar = threadIdx.x >> 8;            // 0 or 1
    const int x = bx * 16 + lx;
    const int y = by * 16 + ly;

    const int own_base = (ly + H) * YS + (lx + H);

#pragma unroll 2
    for (int k = 0; k < 8; ++k) {
        const int zi = 2 * k + zpar;              // 0..15
        const int z  = bz * 16 + zi;

        uint2 pv = sm[(zi + H) * ZS + own_base];
        __half2 pv0 = *(const __half2*)&pv.x;
        __half2 pv1 = *(const __half2*)&pv.y;
        float2 f0 = __half22float2(pv0);
        float vz = f0.x, vy = f0.y;
        float vx = __low2float(pv1);

        float phz = (float)z + vz;
        float phy = (float)y + vy;
        float phx = (float)x + vx;

        int iz = __float2int_rd(phz);
        int iy = __float2int_rd(phy);
        int ix = __float2int_rd(phx);
        float wz1 = phz - (float)iz;
        float wy1 = phy - (float)iy;
        float wx1 = phx - (float)ix;
        float wz0 = 1.0f - wz1, wy0 = 1.0f - wy1, wx0 = 1.0f - wx1;

        // local corner coords; clamps are memory-safety insurance only
        int lz0 = min(max(iz - gz0, 0), EXT - 2);
        int ly0 = min(max(iy - gy0, 0), EXT - 2);
        int lx0 = min(max(ix - gx0, 0), EXT - 2);

        int p00 = lz0 * ZS + ly0 * YS + lx0;
        int p01 = p00 + YS;
        int p10 = p00 + ZS;
        int p11 = p10 + YS;

        uint2 q[8];
        q[0] = sm[p00];     q[1] = sm[p00 + 1];
        q[2] = sm[p01];     q[3] = sm[p01 + 1];
        q[4] = sm[p10];     q[5] = sm[p10 + 1];
        q[6] = sm[p11];     q[7] = sm[p11 + 1];

        __half2 wzy2[4];
        wzy2[0] = __float2half2_rn(wz0 * wy0);
        wzy2[1] = __float2half2_rn(wz0 * wy1);
        wzy2[2] = __float2half2_rn(wz1 * wy0);
        wzy2[3] = __float2half2_rn(wz1 * wy1);
        const __half2 wxlo = __float2half2_rn(wx0);
        const __half2 wxhi = __float2half2_rn(wx1);

        const __half2 h2zero = __float2half2_rn(0.f);
        __half2 acc0a = h2zero, acc1a = h2zero;
        __half2 acc0b = h2zero, acc1b = h2zero;
#pragma unroll
        for (int rr = 0; rr < 2; ++rr) {
            __half2 wlo = __hmul2(wzy2[rr], wxlo);
            __half2 whi = __hmul2(wzy2[rr], wxhi);
            acc0a = __hfma2(wlo, *(const __half2*)&q[2 * rr].x, acc0a);
            acc1a = __hfma2(wlo, *(const __half2*)&q[2 * rr].y, acc1a);
            acc0a = __hfma2(whi, *(const __half2*)&q[2 * rr + 1].x, acc0a);
            acc1a = __hfma2(whi, *(const __half2*)&q[2 * rr + 1].y, acc1a);
        }
#pragma unroll
        for (int rr = 2; rr < 4; ++rr) {
            __half2 wlo = __hmul2(wzy2[rr], wxlo);
            __half2 whi = __hmul2(wzy2[rr], wxhi);
            acc0b = __hfma2(wlo, *(const __half2*)&q[2 * rr].x, acc0b);
            acc1b = __hfma2(wlo, *(const __half2*)&q[2 * rr].y, acc1b);
            acc0b = __hfma2(whi, *(const __half2*)&q[2 * rr + 1].x, acc0b);
            acc1b = __hfma2(whi, *(const __half2*)&q[2 * rr + 1].y, acc1b);
        }
        __half2 acc0 = __hadd2(acc0a, acc0b);
        __half2 acc1 = __hadd2(acc1a, acc1b);

        float2 s0 = __half22float2(acc0);
        float oz = vz + s0.x;
        float oy = vy + s0.y;
        float ox = vx + __low2float(acc1);

        dst[base + (z << 14) + (y << 7) + x] = pack_v(oz, oy, ox);
    }
}

// ================= flat last step (any |v|), 2 z-split voxels/thread ================
struct Setup {
    int rows[4];
    int x0, x1;
    __half2 wzy2[4];
    __half2 wxlo, wxhi;
    float vz, vy, vx;
};

static __device__ __forceinline__ Setup prep(int base, int z, int y, int x, uint2 pv)
{
    Setup s;
    __half2 pv0 = *(const __half2*)&pv.x;
    __half2 pv1 = *(const __half2*)&pv.y;
    float2 f0 = __half22float2(pv0);
    s.vz = f0.x; s.vy = f0.y;
    s.vx = __low2float(pv1);

    float phz = (float)z + s.vz;
    float phy = (float)y + s.vy;
    float phx = (float)x + s.vx;

    int iz = __float2int_rd(phz);
    int iy = __float2int_rd(phy);
    int ix = __float2int_rd(phx);
    float wz1 = phz - (float)iz;
    float wy1 = phy - (float)iy;
    float wx1 = phx - (float)ix;
    float wz0 = 1.0f - wz1, wy0 = 1.0f - wy1, wx0 = 1.0f - wx1;

    int z0 = iz & 127, z1 = (iz + 1) & 127;
    int y0 = iy & 127, y1 = (iy + 1) & 127;
    s.x0 = ix & 127;
    s.x1 = (ix + 1) & 127;

    s.rows[0] = base + (z0 << 14) + (y0 << 7);
    s.rows[1] = base + (z0 << 14) + (y1 << 7);
    s.rows[2] = base + (z1 << 14) + (y0 << 7);
    s.rows[3] = base + (z1 << 14) + (y1 << 7);

    s.wzy2[0] = __float2half2_rn(wz0 * wy0);
    s.wzy2[1] = __float2half2_rn(wz0 * wy1);
    s.wzy2[2] = __float2half2_rn(wz1 * wy0);
    s.wzy2[3] = __float2half2_rn(wz1 * wy1);
    s.wxlo = __float2half2_rn(wx0);
    s.wxhi = __float2half2_rn(wx1);
    return s;
}

static __device__ __forceinline__ void accum(const Setup& s, const uint2* q,
                                             float& oz, float& oy, float& ox)
{
    const __half2 h2zero = __float2half2_rn(0.f);
    __half2 acc0a = h2zero, acc1a = h2zero;
    __half2 acc0b = h2zero, acc1b = h2zero;
#pragma unroll
    for (int rr = 0; rr < 2; ++rr) {
        __half2 wlo = __hmul2(s.wzy2[rr], s.wxlo);
        __half2 whi = __hmul2(s.wzy2[rr], s.wxhi);
        acc0a = __hfma2(wlo, *(const __half2*)&q[2 * rr].x, acc0a);
        acc1a = __hfma2(wlo, *(const __half2*)&q[2 * rr].y, acc1a);
        acc0a = __hfma2(whi, *(const __half2*)&q[2 * rr + 1].x, acc0a);
        acc1a = __hfma2(whi, *(const __half2*)&q[2 * rr + 1].y, acc1a);
    }
#pragma unroll
    for (int rr = 2; rr < 4; ++rr) {
        __half2 wlo = __hmul2(s.wzy2[rr], s.wxlo);
        __half2 whi = __hmul2(s.wzy2[rr], s.wxhi);
        acc0b = __hfma2(wlo, *(const __half2*)&q[2 * rr].x, acc0b);
        acc1b = __hfma2(wlo, *(const __half2*)&q[2 * rr].y, acc1b);
        acc0b = __hfma2(whi, *(const __half2*)&q[2 * rr + 1].x, acc0b);
        acc1b = __hfma2(whi, *(const __half2*)&q[2 * rr + 1].y, acc1b);
    }
    __half2 acc0 = __hadd2(acc0a, acc0b);
    __half2 acc1 = __hadd2(acc1a, acc1b);

    float2 s0 = __half22float2(acc0);
    oz = s.vz + s0.x;
    oy = s.vy + s0.y;
    ox = s.vx + __low2float(acc1);
}

__global__ __launch_bounds__(256)
void gridexp_last(const uint2* __restrict__ src, float* __restrict__ dst3)
{
    const int t = blockIdx.x * 256 + threadIdx.x;     // 0 .. N_VOX/2-1
    const int b = t >> 20;
    const int r = t & ((1 << 20) - 1);
    const int z = r >> 14;                            // 0..63
    const int y = (r >> 7) & 127;
    const int x = r & 127;
    const int base = b << 21;
    const int idx0 = base + r;
    const int idx1 = idx0 + ZHALF;

    uint2 pv0 = __ldg(src + idx0);
    uint2 pv1 = __ldg(src + idx1);

    Setup s0 = prep(base, z,      y, x, pv0);
    Setup s1 = prep(base, z + 64, y, x, pv1);

    uint2 q0[8], q1[8];
#pragma unroll
    for (int rr = 0; rr < 4; ++rr) {
        q0[2 * rr + 0] = __ldg(src + s0.rows[rr] + s0.x0);
        q0[2 * rr + 1] = __ldg(src + s0.rows[rr] + s0.x1);
    }
#pragma unroll
    for (int rr = 0; rr < 4; ++rr) {
        q1[2 * rr + 0] = __ldg(src + s1.rows[rr] + s1.x0);
        q1[2 * rr + 1] = __ldg(src + s1.rows[rr] + s1.x1);
    }

    float oz0, oy0, ox0, oz1, oy1, ox1;
    accum(s0, q0, oz0, oy0, ox0);
    accum(s1, q1, oz1, oy1, ox1);

    float* o0 = dst3 + (size_t)idx0 * 3;
    o0[0] = oz0 + (float)z;
    o0[1] = oy0 + (float)y;
    o0[2] = ox0 + (float)x;
    float* o1 = dst3 + (size_t)idx1 * 3;
    o1[0] = oz1 + (float)(z + 64);
    o1[1] = oy1 + (float)y;
    o1[2] = ox1 + (float)x;
}

extern "C" void kernel_launch(void* const* d_in, const int* in_sizes, int n_in,
                              void* d_out, int out_size)
{
    (void)in_sizes; (void)n_in; (void)out_size;
    const float* vel = (const float*)d_in[0];
    float* out = (float*)d_out;

    uint2* bufA = nullptr;
    uint2* bufB = nullptr;
    cudaGetSymbolAddress((void**)&bufA, g_bufA);
    cudaGetSymbolAddress((void**)&bufB, g_bufB);

    // dynamic smem sizes: H=1 -> 18*19*18 elems, H=2 -> 20*21*20 elems (uint2 = 8B)
    const int smem1 = 18 * 19 * 18 * 8;   // 49248 B
    const int smem2 = 20 * 21 * 20 * 8;   // 67200 B
    cudaFuncSetAttribute(gridexp_tile<1>, cudaFuncAttributeMaxDynamicSharedMemorySize, smem1);
    cudaFuncSetAttribute(gridexp_tile<2>, cudaFuncAttributeMaxDynamicSharedMemorySize, smem2);

    const float scale = 1.0f / 256.0f;   // 1 / 2^STEPS, STEPS = 8

    convert_kernel<<<(N_VOX / 4 + 255) / 256, 256>>>(vel, bufA, scale);

    dim3 tgrid(8, 8, 16);                // 8^3 tiles x 2 batches
    uint2* cur = bufA;
    uint2* nxt = bufB;

    // steps 0-4: |v| < 1  -> halo 1
    for (int i = 0; i < 5; ++i) {
        gridexp_tile<1><<<tgrid, 512, smem1>>>(cur, nxt);
        uint2* t = cur; cur = nxt; nxt = t;
    }
    // steps 5-6: |v| < 2  -> halo 2
    for (int i = 0; i < 2; ++i) {
        gridexp_tile<2><<<tgrid, 512, smem2>>>(cur, nxt);
        uint2* t = cur; cur = nxt; nxt = t;
    }
    // step 7: unbounded |v| -> flat global-gather kernel, fused identity + fp32 out
    gridexp_last<<<(N_VOX / 2) / 256, 256>>>(cur, out);
}

// round 15
// speedup vs baseline: 1.0072x; 1.0072x over previous
#include <cuda_runtime.h>
#include <cuda_fp16.h>
#include <cstdint>

// Problem geometry: velocity (B=2, D=128, H=128, W=128, C=3) float32
#define B_  2
#define DIM 128
#define VOX_PER_B (DIM * DIM * DIM)          // 2097152 = 1<<21
#define N_VOX (B_ * VOX_PER_B)               // 4194304
#define ZHALF (64 << 14)

// Persistent launch shape: one wave, 8 blocks/SM on 148 SMs
#define PBLOCKS 1184
#define PTHREADS 256
#define PSTRIDE (PBLOCKS * PTHREADS)         // 303104

// Ping-pong scratch: 8 B/voxel = (half2(vz,vy), half2(vx,0)) packed in uint2
__device__ uint2 g_bufA[N_VOX];
__device__ uint2 g_bufB[N_VOX];

static __device__ __forceinline__ uint2 pack_v(float vz, float vy, float vx)
{
    __half2 h0 = __floats2half2_rn(vz, vy);
    __half2 h1 = __floats2half2_rn(vx, 0.f);
    uint2 r;
    r.x = *(const unsigned int*)&h0;
    r.y = *(const unsigned int*)&h1;
    return r;
}

// -------- convert: float3 AoS fp32 input -> packed fp16, fused 1/2^STEPS scale --------
__global__ __launch_bounds__(PTHREADS)
void convert_kernel(const float* __restrict__ in, uint2* __restrict__ out, float s)
{
    const float4* in4 = (const float4*)in;
    for (int t = blockIdx.x * PTHREADS + threadIdx.x; t < N_VOX / 4; t += PSTRIDE) {
        float4 a = in4[t * 3 + 0];
        float4 b = in4[t * 3 + 1];
        float4 c = in4[t * 3 + 2];
        out[t * 4 + 0] = pack_v(a.x * s, a.y * s, a.z * s);
        out[t * 4 + 1] = pack_v(a.w * s, b.x * s, b.y * s);
        out[t * 4 + 2] = pack_v(b.z * s, b.w * s, c.x * s);
        out[t * 4 + 3] = pack_v(c.y * s, c.z * s, c.w * s);
    }
}

// interpolate one voxel: fp32 own value + weights, half2 gather accumulate
static __device__ __forceinline__ void interp_one(
    const uint2* __restrict__ src, int base, int z, int y, int x,
    uint2 pv, float& oz, float& oy, float& ox)
{
    __half2 pv0 = *(const __half2*)&pv.x;
    __half2 pv1 = *(const __half2*)&pv.y;
    float2 f0 = __half22float2(pv0);
    float vz = f0.x, vy = f0.y;
    float vx = __low2float(pv1);

    float phz = (float)z + vz;
    float phy = (float)y + vy;
    float phx = (float)x + vx;

    int iz = __float2int_rd(phz);
    int iy = __float2int_rd(phy);
    int ix = __float2int_rd(phx);
    float wz1 = phz - (float)iz;
    float wy1 = phy - (float)iy;
    float wx1 = phx - (float)ix;
    float wz0 = 1.0f - wz1, wy0 = 1.0f - wy1, wx0 = 1.0f - wx1;

    int z0 = iz & 127, z1 = (iz + 1) & 127;
    int y0 = iy & 127, y1 = (iy + 1) & 127;
    int x0 = ix & 127, x1 = (ix + 1) & 127;

    int rows[4];
    rows[0] = base + (z0 << 14) + (y0 << 7);
    rows[1] = base + (z0 << 14) + (y1 << 7);
    rows[2] = base + (z1 << 14) + (y0 << 7);
    rows[3] = base + (z1 << 14) + (y1 << 7);

    // all 8 loads issued up front
    uint2 q[8];
#pragma unroll
    for (int rr = 0; rr < 4; ++rr) {
        q[2 * rr + 0] = __ldg(src + rows[rr] + x0);
        q[2 * rr + 1] = __ldg(src + rows[rr] + x1);
    }

    __half2 wzy2[4];
    wzy2[0] = __float2half2_rn(wz0 * wy0);
    wzy2[1] = __float2half2_rn(wz0 * wy1);
    wzy2[2] = __float2half2_rn(wz1 * wy0);
    wzy2[3] = __float2half2_rn(wz1 * wy1);
    const __half2 wxlo = __float2half2_rn(wx0);
    const __half2 wxhi = __float2half2_rn(wx1);

    const __half2 h2zero = __float2half2_rn(0.f);
    __half2 acc0a = h2zero, acc1a = h2zero;
    __half2 acc0b = h2zero, acc1b = h2zero;
#pragma unroll
    for (int rr = 0; rr < 2; ++rr) {
        __half2 wlo = __hmul2(wzy2[rr], wxlo);
        __half2 whi = __hmul2(wzy2[rr], wxhi);
        acc0a = __hfma2(wlo, *(const __half2*)&q[2 * rr].x, acc0a);
        acc1a = __hfma2(wlo, *(const __half2*)&q[2 * rr].y, acc1a);
        acc0a = __hfma2(whi, *(const __half2*)&q[2 * rr + 1].x, acc0a);
        acc1a = __hfma2(whi, *(const __half2*)&q[2 * rr + 1].y, acc1a);
    }
#pragma unroll
    for (int rr = 2; rr < 4; ++rr) {
        __half2 wlo = __hmul2(wzy2[rr], wxlo);
        __half2 whi = __hmul2(wzy2[rr], wxhi);
        acc0b = __hfma2(wlo, *(const __half2*)&q[2 * rr].x, acc0b);
        acc1b = __hfma2(wlo, *(const __half2*)&q[2 * rr].y, acc1b);
        acc0b = __hfma2(whi, *(const __half2*)&q[2 * rr + 1].x, acc0b);
        acc1b = __hfma2(whi, *(const __half2*)&q[2 * rr + 1].y, acc1b);
    }
    __half2 acc0 = __hadd2(acc0a, acc0b);
    __half2 acc1 = __hadd2(acc1a, acc1b);

    float2 s0 = __half22float2(acc0);
    oz = vz + s0.x;
    oy = vy + s0.y;
    ox = vx + __low2float(acc1);
}

// -------- persistent squaring step: 2 z-split voxels per loop item --------
__global__ __launch_bounds__(PTHREADS)
void gridexp_step(const uint2* __restrict__ src, uint2* __restrict__ dst)
{
    for (int t = blockIdx.x * PTHREADS + threadIdx.x; t < N_VOX / 2; t += PSTRIDE) {
        const int b = t >> 20;
        const int r = t & ((1 << 20) - 1);
        const int z = r >> 14;                        // 0..63
        const int y = (r >> 7) & 127;
        const int x = r & 127;
        const int base = b << 21;
        const int idx0 = base + r;
        const int idx1 = idx0 + ZHALF;

        uint2 pv0 = __ldg(src + idx0);
        uint2 pv1 = __ldg(src + idx1);

        float oz0, oy0, ox0, oz1, oy1, ox1;
        interp_one(src, base, z,      y, x, pv0, oz0, oy0, ox0);
        interp_one(src, base, z + 64, y, x, pv1, oz1, oy1, ox1);

        dst[idx0] = pack_v(oz0, oy0, ox0);
        dst[idx1] = pack_v(oz1, oy1, ox1);
    }
}

// -------- persistent last step: fused identity-grid add, stride-3 fp32 output --------
__global__ __launch_bounds__(PTHREADS)
void gridexp_last(const uint2* __restrict__ src, float* __restrict__ dst3)
{
    for (int t = blockIdx.x * PTHREADS + threadIdx.x; t < N_VOX / 2; t += PSTRIDE) {
        const int b = t >> 20;
        const int r = t & ((1 << 20) - 1);
        const int z = r >> 14;
        const int y = (r >> 7) & 127;
        const int x = r & 127;
        const int base = b << 21;
        const int idx0 = base + r;
        const int idx1 = idx0 + ZHALF;

        uint2 pv0 = __ldg(src + idx0);
        uint2 pv1 = __ldg(src + idx1);

        float oz0, oy0, ox0, oz1, oy1, ox1;
        interp_one(src, base, z,      y, x, pv0, oz0, oy0, ox0);
        interp_one(src, base, z + 64, y, x, pv1, oz1, oy1, ox1);

        float* o0 = dst3 + (size_t)idx0 * 3;
        o0[0] = oz0 + (float)z;
        o0[1] = oy0 + (float)y;
        o0[2] = ox0 + (float)x;
        float* o1 = dst3 + (size_t)idx1 * 3;
        o1[0] = oz1 + (float)(z + 64);
        o1[1] = oy1 + (float)y;
        o1[2] = ox1 + (float)x;
    }
}

extern "C" void kernel_launch(void* const* d_in, const int* in_sizes, int n_in,
                              void* d_out, int out_size)
{
    (void)in_sizes; (void)n_in; (void)out_size;
    const float* vel = (const float*)d_in[0];
    float* out = (float*)d_out;

    uint2* bufA = nullptr;
    uint2* bufB = nullptr;
    cudaGetSymbolAddress((void**)&bufA, g_bufA);
    cudaGetSymbolAddress((void**)&bufB, g_bufB);

    const float scale = 1.0f / 256.0f;   // 1 / 2^STEPS, STEPS = 8

    convert_kernel<<<PBLOCKS, PTHREADS>>>(vel, bufA, scale);

    uint2* cur = bufA;
    uint2* nxt = bufB;
    for (int i = 0; i < 7; ++i) {
        gridexp_step<<<PBLOCKS, PTHREADS>>>(cur, nxt);
        uint2* t = cur; cur = nxt; nxt = t;
    }
    gridexp_last<<<PBLOCKS, PTHREADS>>>(cur, out);
}

// round 16
// speedup vs baseline: 1.1920x; 1.1835x over previous
#include <cuda_runtime.h>
#include <cuda_fp16.h>
#include <cstdint>

// Problem geometry: velocity (B=2, D=128, H=128, W=128, C=3) float32
#define B_  2
#define DIM 128
#define VOX_PER_B (DIM * DIM * DIM)          // 2097152 = 1<<21
#define N_VOX (B_ * VOX_PER_B)               // 4194304
#define ZHALF (64 << 14)

// Ping-pong scratch: 8 B/voxel = (half2(vz,vy), half2(vx,0)) packed in uint2
__device__ uint2 g_bufA[N_VOX];
__device__ uint2 g_bufB[N_VOX];

static __device__ __forceinline__ uint2 pack_v(float vz, float vy, float vx)
{
    __half2 h0 = __floats2half2_rn(vz, vy);
    __half2 h1 = __floats2half2_rn(vx, 0.f);
    uint2 r;
    r.x = *(const unsigned int*)&h0;
    r.y = *(const unsigned int*)&h1;
    return r;
}

// -------- convert: float3 AoS fp32 input -> packed fp16, fused 1/2^STEPS scale --------
__global__ __launch_bounds__(256)
void convert_kernel(const float* __restrict__ in, uint2* __restrict__ out, float s)
{
    int t = blockIdx.x * blockDim.x + threadIdx.x;   // one thread = 4 voxels
    if (t >= N_VOX / 4) return;
    const float4* in4 = (const float4*)in;
    float4 a = in4[t * 3 + 0];
    float4 b = in4[t * 3 + 1];
    float4 c = in4[t * 3 + 2];
    out[t * 4 + 0] = pack_v(a.x * s, a.y * s, a.z * s);
    out[t * 4 + 1] = pack_v(a.w * s, b.x * s, b.y * s);
    out[t * 4 + 2] = pack_v(b.z * s, b.w * s, c.x * s);
    out[t * 4 + 3] = pack_v(c.y * s, c.z * s, c.w * s);
}

// ============ middle squaring step: R5 design (1 voxel/thread, regs ~30) ============
__global__ __launch_bounds__(256)
void gridexp_step(const uint2* __restrict__ src, uint2* __restrict__ dst)
{
    const int idx = blockIdx.x * 256 + threadIdx.x;   // grid sized exactly

    const int b = idx >> 21;
    const int r = idx & (VOX_PER_B - 1);
    const int z = r >> 14;
    const int y = (r >> 7) & 127;
    const int x = r & 127;

    // own value: fp32 (phi needs precision)
    uint2 pv = src[idx];
    __half2 pv0 = *(const __half2*)&pv.x;
    __half2 pv1 = *(const __half2*)&pv.y;
    float2 f0 = __half22float2(pv0);
    float vz = f0.x, vy = f0.y;
    float vx = __low2float(pv1);

    float phz = (float)z + vz;
    float phy = (float)y + vy;
    float phx = (float)x + vx;

    int iz = __float2int_rd(phz);
    int iy = __float2int_rd(phy);
    int ix = __float2int_rd(phx);
    float wz1 = phz - (float)iz;
    float wy1 = phy - (float)iy;
    float wx1 = phx - (float)ix;
    float wz0 = 1.0f - wz1, wy0 = 1.0f - wy1, wx0 = 1.0f - wx1;

    int z0 = iz & 127, z1 = (iz + 1) & 127;
    int y0 = iy & 127, y1 = (iy + 1) & 127;
    int x0 = ix & 127, x1 = (ix + 1) & 127;

    const int base = b << 21;
    int row00 = base + (z0 << 14) + (y0 << 7);
    int row01 = base + (z0 << 14) + (y1 << 7);
    int row10 = base + (z1 << 14) + (y0 << 7);
    int row11 = base + (z1 << 14) + (y1 << 7);
    int rows[4] = { row00, row01, row10, row11 };

    __half2 wzy2[4];
    wzy2[0] = __float2half2_rn(wz0 * wy0);
    wzy2[1] = __float2half2_rn(wz0 * wy1);
    wzy2[2] = __float2half2_rn(wz1 * wy0);
    wzy2[3] = __float2half2_rn(wz1 * wy1);
    const __half2 wxlo = __float2half2_rn(wx0);
    const __half2 wxhi = __float2half2_rn(wx1);
    int xo[2] = { x0, x1 };

    __half2 acc0 = __float2half2_rn(0.f);   // (sz, sy)
    __half2 acc1 = __float2half2_rn(0.f);   // (sx, ·)

#pragma unroll
    for (int rr = 0; rr < 4; ++rr) {
#pragma unroll
        for (int d = 0; d < 2; ++d) {
            uint2 q = __ldg(src + rows[rr] + xo[d]);
            __half2 w2 = __hmul2(wzy2[rr], d ? wxhi : wxlo);
            acc0 = __hfma2(w2, *(const __half2*)&q.x, acc0);
            acc1 = __hfma2(w2, *(const __half2*)&q.y, acc1);
        }
    }

    float2 s0 = __half22float2(acc0);
    float oz = vz + s0.x;
    float oy = vy + s0.y;
    float ox = vx + __low2float(acc1);

    dst[idx] = pack_v(oz, oy, ox);
}

// ============ last step: R10/R13 design (2 z-split voxels/thread, fp32 out) =========
struct Setup {
    int rows[4];
    int x0, x1;
    __half2 wzy2[4];
    __half2 wxlo, wxhi;
    float vz, vy, vx;
};

static __device__ __forceinline__ Setup prep(int base, int z, int y, int x, uint2 pv)
{
    Setup s;
    __half2 pv0 = *(const __half2*)&pv.x;
    __half2 pv1 = *(const __half2*)&pv.y;
    float2 f0 = __half22float2(pv0);
    s.vz = f0.x; s.vy = f0.y;
    s.vx = __low2float(pv1);

    float phz = (float)z + s.vz;
    float phy = (float)y + s.vy;
    float phx = (float)x + s.vx;

    int iz = __float2int_rd(phz);
    int iy = __float2int_rd(phy);
    int ix = __float2int_rd(phx);
    float wz1 = phz - (float)iz;
    float wy1 = phy - (float)iy;
    float wx1 = phx - (float)ix;
    float wz0 = 1.0f - wz1, wy0 = 1.0f - wy1, wx0 = 1.0f - wx1;

    int z0 = iz & 127, z1 = (iz + 1) & 127;
    int y0 = iy & 127, y1 = (iy + 1) & 127;
    s.x0 = ix & 127;
    s.x1 = (ix + 1) & 127;

    s.rows[0] = base + (z0 << 14) + (y0 << 7);
    s.rows[1] = base + (z0 << 14) + (y1 << 7);
    s.rows[2] = base + (z1 << 14) + (y0 << 7);
    s.rows[3] = base + (z1 << 14) + (y1 << 7);

    s.wzy2[0] = __float2half2_rn(wz0 * wy0);
    s.wzy2[1] = __float2half2_rn(wz0 * wy1);
    s.wzy2[2] = __float2half2_rn(wz1 * wy0);
    s.wzy2[3] = __float2half2_rn(wz1 * wy1);
    s.wxlo = __float2half2_rn(wx0);
    s.wxhi = __float2half2_rn(wx1);
    return s;
}

static __device__ __forceinline__ void accum(const Setup& s, const uint2* q,
                                             float& oz, float& oy, float& ox)
{
    const __half2 h2zero = __float2half2_rn(0.f);
    __half2 acc0a = h2zero, acc1a = h2zero;
    __half2 acc0b = h2zero, acc1b = h2zero;
#pragma unroll
    for (int rr = 0; rr < 2; ++rr) {
        __half2 wlo = __hmul2(s.wzy2[rr], s.wxlo);
        __half2 whi = __hmul2(s.wzy2[rr], s.wxhi);
        acc0a = __hfma2(wlo, *(const __half2*)&q[2 * rr].x, acc0a);
        acc1a = __hfma2(wlo, *(const __half2*)&q[2 * rr].y, acc1a);
        acc0a = __hfma2(whi, *(const __half2*)&q[2 * rr + 1].x, acc0a);
        acc1a = __hfma2(whi, *(const __half2*)&q[2 * rr + 1].y, acc1a);
    }
#pragma unroll
    for (int rr = 2; rr < 4; ++rr) {
        __half2 wlo = __hmul2(s.wzy2[rr], s.wxlo);
        __half2 whi = __hmul2(s.wzy2[rr], s.wxhi);
        acc0b = __hfma2(wlo, *(const __half2*)&q[2 * rr].x, acc0b);
        acc1b = __hfma2(wlo, *(const __half2*)&q[2 * rr].y, acc1b);
        acc0b = __hfma2(whi, *(const __half2*)&q[2 * rr + 1].x, acc0b);
        acc1b = __hfma2(whi, *(const __half2*)&q[2 * rr + 1].y, acc1b);
    }
    __half2 acc0 = __hadd2(acc0a, acc0b);
    __half2 acc1 = __hadd2(acc1a, acc1b);

    float2 s0 = __half22float2(acc0);
    oz = s.vz + s0.x;
    oy = s.vy + s0.y;
    ox = s.vx + __low2float(acc1);
}

__global__ __launch_bounds__(256)
void gridexp_last(const uint2* __restrict__ src, float* __restrict__ dst3)
{
    const int t = blockIdx.x * 256 + threadIdx.x;     // 0 .. N_VOX/2-1
    const int b = t >> 20;
    const int r = t & ((1 << 20) - 1);
    const int z = r >> 14;                            // 0..63
    const int y = (r >> 7) & 127;
    const int x = r & 127;
    const int base = b << 21;
    const int idx0 = base + r;
    const int idx1 = idx0 + ZHALF;

    uint2 pv0 = __ldg(src + idx0);
    uint2 pv1 = __ldg(src + idx1);

    Setup s0 = prep(base, z,      y, x, pv0);
    Setup s1 = prep(base, z + 64, y, x, pv1);

    uint2 q0[8], q1[8];
#pragma unroll
    for (int rr = 0; rr < 4; ++rr) {
        q0[2 * rr + 0] = __ldg(src + s0.rows[rr] + s0.x0);
        q0[2 * rr + 1] = __ldg(src + s0.rows[rr] + s0.x1);
    }
#pragma unroll
    for (int rr = 0; rr < 4; ++rr) {
        q1[2 * rr + 0] = __ldg(src + s1.rows[rr] + s1.x0);
        q1[2 * rr + 1] = __ldg(src + s1.rows[rr] + s1.x1);
    }

    float oz0, oy0, ox0, oz1, oy1, ox1;
    accum(s0, q0, oz0, oy0, ox0);
    accum(s1, q1, oz1, oy1, ox1);

    float* o0 = dst3 + (size_t)idx0 * 3;
    o0[0] = oz0 + (float)z;
    o0[1] = oy0 + (float)y;
    o0[2] = ox0 + (float)x;
    float* o1 = dst3 + (size_t)idx1 * 3;
    o1[0] = oz1 + (float)(z + 64);
    o1[1] = oy1 + (float)y;
    o1[2] = ox1 + (float)x;
}

extern "C" void kernel_launch(void* const* d_in, const int* in_sizes, int n_in,
                              void* d_out, int out_size)
{
    (void)in_sizes; (void)n_in; (void)out_size;
    const float* vel = (const float*)d_in[0];
    float* out = (float*)d_out;

    uint2* bufA = nullptr;
    uint2* bufB = nullptr;
    cudaGetSymbolAddress((void**)&bufA, g_bufA);
    cudaGetSymbolAddress((void**)&bufB, g_bufB);

    const float scale = 1.0f / 256.0f;   // 1 / 2^STEPS, STEPS = 8
    const int threads = 256;

    convert_kernel<<<(N_VOX / 4 + threads - 1) / threads, threads>>>(vel, bufA, scale);

    const int blocks = N_VOX / threads;  // exact: 16384
    uint2* cur = bufA;
    uint2* nxt = bufB;
    for (int i = 0; i < 7; ++i) {
        gridexp_step<<<blocks, threads>>>(cur, nxt);
        uint2* t = cur; cur = nxt; nxt = t;
    }
    gridexp_last<<<(N_VOX / 2) / threads, threads>>>(cur, out);
}

// round 17
// speedup vs baseline: 1.1963x; 1.0036x over previous
#include <cuda_runtime.h>
#include <cuda_fp16.h>
#include <cstdint>

// Problem geometry: velocity (B=2, D=128, H=128, W=128, C=3) float32
#define B_  2
#define DIM 128
#define VOX_PER_B (DIM * DIM * DIM)          // 2097152 = 1<<21
#define N_VOX (B_ * VOX_PER_B)               // 4194304
#define ZHALF (64 << 14)

// Ping-pong scratch: 8 B/voxel = (half2(vz,vy), half2(vx,0)) packed in uint2
__device__ uint2 g_bufA[N_VOX];
__device__ uint2 g_bufB[N_VOX];

static __device__ __forceinline__ uint2 pack_v(float vz, float vy, float vx)
{
    __half2 h0 = __floats2half2_rn(vz, vy);
    __half2 h1 = __floats2half2_rn(vx, 0.f);
    uint2 r;
    r.x = *(const unsigned int*)&h0;
    r.y = *(const unsigned int*)&h1;
    return r;
}

// -------- convert: float3 AoS fp32 input -> packed fp16, fused 1/2^STEPS scale --------
__global__ __launch_bounds__(256)
void convert_kernel(const float* __restrict__ in, uint2* __restrict__ out, float s)
{
    int t = blockIdx.x * blockDim.x + threadIdx.x;   // one thread = 4 voxels
    if (t >= N_VOX / 4) return;
    const float4* in4 = (const float4*)in;
    float4 a = in4[t * 3 + 0];
    float4 b = in4[t * 3 + 1];
    float4 c = in4[t * 3 + 2];
    out[t * 4 + 0] = pack_v(a.x * s, a.y * s, a.z * s);
    out[t * 4 + 1] = pack_v(a.w * s, b.x * s, b.y * s);
    out[t * 4 + 2] = pack_v(b.z * s, b.w * s, c.x * s);
    out[t * 4 + 3] = pack_v(c.y * s, c.z * s, c.w * s);
}

// ----- shared interpolation machinery (R13's measured-best design) -----
struct Setup {
    int rows[4];
    int x0, x1;
    __half2 wzy2[4];
    __half2 wxlo, wxhi;
    float vz, vy, vx;
};

static __device__ __forceinline__ Setup prep(int base, int z, int y, int x, uint2 pv)
{
    Setup s;
    __half2 pv0 = *(const __half2*)&pv.x;
    __half2 pv1 = *(const __half2*)&pv.y;
    float2 f0 = __half22float2(pv0);
    s.vz = f0.x; s.vy = f0.y;
    s.vx = __low2float(pv1);

    float phz = (float)z + s.vz;
    float phy = (float)y + s.vy;
    float phx = (float)x + s.vx;

    int iz = __float2int_rd(phz);
    int iy = __float2int_rd(phy);
    int ix = __float2int_rd(phx);
    float wz1 = phz - (float)iz;
    float wy1 = phy - (float)iy;
    float wx1 = phx - (float)ix;
    float wz0 = 1.0f - wz1, wy0 = 1.0f - wy1, wx0 = 1.0f - wx1;

    int z0 = iz & 127, z1 = (iz + 1) & 127;
    int y0 = iy & 127, y1 = (iy + 1) & 127;
    s.x0 = ix & 127;
    s.x1 = (ix + 1) & 127;

    s.rows[0] = base + (z0 << 14) + (y0 << 7);
    s.rows[1] = base + (z0 << 14) + (y1 << 7);
    s.rows[2] = base + (z1 << 14) + (y0 << 7);
    s.rows[3] = base + (z1 << 14) + (y1 << 7);

    s.wzy2[0] = __float2half2_rn(wz0 * wy0);
    s.wzy2[1] = __float2half2_rn(wz0 * wy1);
    s.wzy2[2] = __float2half2_rn(wz1 * wy0);
    s.wzy2[3] = __float2half2_rn(wz1 * wy1);
    s.wxlo = __float2half2_rn(wx0);
    s.wxhi = __float2half2_rn(wx1);
    return s;
}

static __device__ __forceinline__ void accum(const Setup& s, const uint2* q,
                                             float& oz, float& oy, float& ox)
{
    const __half2 h2zero = __float2half2_rn(0.f);
    __half2 acc0a = h2zero, acc1a = h2zero;
    __half2 acc0b = h2zero, acc1b = h2zero;
#pragma unroll
    for (int rr = 0; rr < 2; ++rr) {
        __half2 wlo = __hmul2(s.wzy2[rr], s.wxlo);
        __half2 whi = __hmul2(s.wzy2[rr], s.wxhi);
        acc0a = __hfma2(wlo, *(const __half2*)&q[2 * rr].x, acc0a);
        acc1a = __hfma2(wlo, *(const __half2*)&q[2 * rr].y, acc1a);
        acc0a = __hfma2(whi, *(const __half2*)&q[2 * rr + 1].x, acc0a);
        acc1a = __hfma2(whi, *(const __half2*)&q[2 * rr + 1].y, acc1a);
    }
#pragma unroll
    for (int rr = 2; rr < 4; ++rr) {
        __half2 wlo = __hmul2(s.wzy2[rr], s.wxlo);
        __half2 whi = __hmul2(s.wzy2[rr], s.wxhi);
        acc0b = __hfma2(wlo, *(const __half2*)&q[2 * rr].x, acc0b);
        acc1b = __hfma2(wlo, *(const __half2*)&q[2 * rr].y, acc1b);
        acc0b = __hfma2(whi, *(const __half2*)&q[2 * rr + 1].x, acc0b);
        acc1b = __hfma2(whi, *(const __half2*)&q[2 * rr + 1].y, acc1b);
    }
    __half2 acc0 = __hadd2(acc0a, acc0b);
    __half2 acc1 = __hadd2(acc1a, acc1b);

    float2 s0 = __half22float2(acc0);
    oz = s.vz + s0.x;
    oy = s.vy + s0.y;
    ox = s.vx + __low2float(acc1);
}

// -------- middle squaring step: 2 z-split voxels/thread, 16-load batch (R13) --------
__global__ __launch_bounds__(256)
void gridexp_step(const uint2* __restrict__ src, uint2* __restrict__ dst)
{
    const int t = blockIdx.x * 256 + threadIdx.x;     // 0 .. N_VOX/2-1
    const int b = t >> 20;
    const int r = t & ((1 << 20) - 1);
    const int z = r >> 14;                            // 0..63
    const int y = (r >> 7) & 127;
    const int x = r & 127;
    const int base = b << 21;
    const int idx0 = base + r;
    const int idx1 = idx0 + ZHALF;

    uint2 pv0 = __ldg(src + idx0);
    uint2 pv1 = __ldg(src + idx1);

    Setup s0 = prep(base, z,      y, x, pv0);
    Setup s1 = prep(base, z + 64, y, x, pv1);

    uint2 q0[8], q1[8];
#pragma unroll
    for (int rr = 0; rr < 4; ++rr) {
        q0[2 * rr + 0] = __ldg(src + s0.rows[rr] + s0.x0);
        q0[2 * rr + 1] = __ldg(src + s0.rows[rr] + s0.x1);
    }
#pragma unroll
    for (int rr = 0; rr < 4; ++rr) {
        q1[2 * rr + 0] = __ldg(src + s1.rows[rr] + s1.x0);
        q1[2 * rr + 1] = __ldg(src + s1.rows[rr] + s1.x1);
    }

    float oz0, oy0, ox0, oz1, oy1, ox1;
    accum(s0, q0, oz0, oy0, ox0);
    accum(s1, q1, oz1, oy1, ox1);

    dst[idx0] = pack_v(oz0, oy0, ox0);
    dst[idx1] = pack_v(oz1, oy1, ox1);
}

// -------- last step: smem-staged coalesced float4 output stores --------
__global__ __launch_bounds__(256)
void gridexp_last(const uint2* __restrict__ src, float* __restrict__ dst3)
{
    __shared__ float sb[1536];                        // 2 segments x 256 voxels x 3 floats

    const int tid = threadIdx.x;
    const int t = blockIdx.x * 256 + tid;             // 0 .. N_VOX/2-1
    const int b = t >> 20;
    const int r = t & ((1 << 20) - 1);
    const int z = r >> 14;                            // 0..63
    const int y = (r >> 7) & 127;
    const int x = r & 127;
    const int base = b << 21;
    const int idx0 = base + r;
    const int idx1 = idx0 + ZHALF;

    uint2 pv0 = __ldg(src + idx0);
    uint2 pv1 = __ldg(src + idx1);

    Setup s0 = prep(base, z,      y, x, pv0);
    Setup s1 = prep(base, z + 64, y, x, pv1);

    uint2 q0[8], q1[8];
#pragma unroll
    for (int rr = 0; rr < 4; ++rr) {
        q0[2 * rr + 0] = __ldg(src + s0.rows[rr] + s0.x0);
        q0[2 * rr + 1] = __ldg(src + s0.rows[rr] + s0.x1);
    }
#pragma unroll
    for (int rr = 0; rr < 4; ++rr) {
        q1[2 * rr + 0] = __ldg(src + s1.rows[rr] + s1.x0);
        q1[2 * rr + 1] = __ldg(src + s1.rows[rr] + s1.x1);
    }

    float oz0, oy0, ox0, oz1, oy1, ox1;
    accum(s0, q0, oz0, oy0, ox0);
    accum(s1, q1, oz1, oy1, ox1);

    // stage results (stride-3 STS, odd stride -> conflict-free)
    sb[tid * 3 + 0] = oz0 + (float)z;
    sb[tid * 3 + 1] = oy0 + (float)y;
    sb[tid * 3 + 2] = ox0 + (float)x;
    sb[768 + tid * 3 + 0] = oz1 + (float)(z + 64);
    sb[768 + tid * 3 + 1] = oy1 + (float)y;
    sb[768 + tid * 3 + 2] = ox1 + (float)x;
    __syncthreads();

    // drain as coalesced float4 stores: 384 float4 total
    // segment 0 base voxel = block's first idx0; segment 1 = +ZHALF
    const int seg0_vox = (blockIdx.x * 256) >= (1 << 20)
                       ? ((1 << 21) + ((blockIdx.x * 256) & ((1 << 20) - 1)))
                       : (blockIdx.x * 256);
    float4* o0 = (float4*)(dst3 + (size_t)seg0_vox * 3);
    float4* o1 = (float4*)(dst3 + ((size_t)seg0_vox + ZHALF) * 3);
    const float4* sb4 = (const float4*)sb;

    // 192 float4 per segment; 256 threads: tid<192 does seg0, tid<192 does seg1 too
    if (tid < 192) {
        o0[tid] = sb4[tid];
        o1[tid] = sb4[192 + tid];
    }
}

extern "C" void kernel_launch(void* const* d_in, const int* in_sizes, int n_in,
                              void* d_out, int out_size)
{
    (void)in_sizes; (void)n_in; (void)out_size;
    const float* vel = (const float*)d_in[0];
    float* out = (float*)d_out;

    uint2* bufA = nullptr;
    uint2* bufB = nullptr;
    cudaGetSymbolAddress((void**)&bufA, g_bufA);
    cudaGetSymbolAddress((void**)&bufB, g_bufB);

    const float scale = 1.0f / 256.0f;   // 1 / 2^STEPS, STEPS = 8
    const int threads = 256;

    convert_kernel<<<(N_VOX / 4 + threads - 1) / threads, threads>>>(vel, bufA, scale);

    const int blocks = (N_VOX / 2) / threads;  // exact: 8192
    uint2* cur = bufA;
    uint2* nxt = bufB;
    for (int i = 0; i < 7; ++i) {
        gridexp_step<<<blocks, threads>>>(cur, nxt);
        uint2* t = cur; cur = nxt; nxt = t;
    }
    gridexp_last<<<blocks, threads>>>(cur, out);
}